// round 1
// baseline (speedup 1.0000x reference)
#include <cuda_runtime.h>
#include <cstdint>
#include <cfloat>

// Problem constants
#define K_CODES 1024
#define DIM     256
#define BATCH   32
#define TLEN    2048
#define NROWS   (BATCH * TLEN)          // 65536
#define QELEMS  ((size_t)BATCH * DIM * TLEN)  // 16777216
#define LOSS_OFF ((size_t)16777216)
#define IDX_OFF  ((size_t)16777217)

#define ROWS_PER_BLK 64
#define KTILE  128
#define DCHUNK 32

// Scratch (no allocations allowed)
__device__ float  g_emb_t[DIM * K_CODES];  // transposed codebook [d][k]
__device__ float  g_esq[K_CODES];          // ||e_k||^2
__device__ double g_loss;

// ---------------------------------------------------------------------------
// prep: transpose codebook, per-code sum of squares, zero loss accumulator
// grid: K_CODES blocks x DIM threads
// ---------------------------------------------------------------------------
__global__ void vq_prep(const float* __restrict__ emb) {
    int k = blockIdx.x;
    int d = threadIdx.x;
    float v = emb[k * DIM + d];
    g_emb_t[(size_t)d * K_CODES + k] = v;

    __shared__ float red[DIM];
    red[d] = v * v;
    __syncthreads();
    #pragma unroll
    for (int s = DIM / 2; s > 0; s >>= 1) {
        if (d < s) red[d] += red[d + s];
        __syncthreads();
    }
    if (d == 0) g_esq[k] = red[0];
    if (k == 0 && d == 0) g_loss = 0.0;
}

// ---------------------------------------------------------------------------
// main: distances + argmin + gather + straight-through write + loss partial
// grid: NROWS / ROWS_PER_BLK = 1024 blocks x 256 threads
// dynamic smem layout:
//   Xs   [DIM][64]        65536 B
//   Es   [DCHUNK][KTILE]  16384 B
//   xs   [64]               256 B
//   redv [64][16]          4096 B
//   redi [64][16]          4096 B
//   bidx [64]               256 B
// ---------------------------------------------------------------------------
__global__ void __launch_bounds__(256)
vq_main(const float* __restrict__ x_in, float* __restrict__ out) {
    extern __shared__ float sm[];
    float* Xs   = sm;                                  // [256][64]
    float* Es   = Xs + DIM * ROWS_PER_BLK;             // [32][128]
    float* xs   = Es + DCHUNK * KTILE;                 // [64]
    float* redv = xs + ROWS_PER_BLK;                   // [64][16]
    int*   redi = (int*)(redv + ROWS_PER_BLK * 16);    // [64][16]
    int*   bidx = redi + ROWS_PER_BLK * 16;            // [64]

    const int blk = blockIdx.x;
    const int b   = blk >> 5;                 // 32 t-chunks per batch entry
    const int t0  = (blk & 31) * ROWS_PER_BLK;
    const int tid = threadIdx.x;

    const float* xbase = x_in + (size_t)b * DIM * TLEN + t0;

    // Load X tile: Xs[d][r] = input[b, d, t0+r]   (coalesced along r)
    #pragma unroll 4
    for (int i = tid; i < DIM * ROWS_PER_BLK; i += 256) {
        int d = i >> 6, r = i & 63;
        Xs[i] = xbase[(size_t)d * TLEN + r];
    }
    __syncthreads();

    // ||x||^2 per row (threads 0..63)
    if (tid < ROWS_PER_BLK) {
        float s = 0.f;
        #pragma unroll 8
        for (int d = 0; d < DIM; ++d) {
            float v = Xs[d * ROWS_PER_BLK + tid];
            s = __fmaf_rn(v, v, s);
        }
        xs[tid] = s;
    }
    __syncthreads();

    const int tr = tid & 15;   // row-group id (4 rows each)
    const int tk = tid >> 4;   // k-group id (8 codes each within a KTILE)
    const int r0 = tr * 4;

    float bestv[4];
    int   besti[4];
    #pragma unroll
    for (int r = 0; r < 4; ++r) { bestv[r] = FLT_MAX; besti[r] = 0; }

    for (int kt = 0; kt < K_CODES / KTILE; ++kt) {
        float acc[4][8];
        #pragma unroll
        for (int r = 0; r < 4; ++r)
            #pragma unroll
            for (int c = 0; c < 8; ++c) acc[r][c] = 0.f;

        for (int dc = 0; dc < DIM / DCHUNK; ++dc) {
            __syncthreads();   // protect Es from previous iteration's readers
            // Load E chunk: Es[dd][kk] = emb_t[dc*32+dd][kt*128+kk] (coalesced)
            #pragma unroll 2
            for (int i = tid; i < DCHUNK * KTILE; i += 256) {
                int dd = i >> 7, kk = i & 127;
                Es[i] = g_emb_t[(size_t)(dc * DCHUNK + dd) * K_CODES + kt * KTILE + kk];
            }
            __syncthreads();

            #pragma unroll
            for (int dd = 0; dd < DCHUNK; ++dd) {
                float4 xv = *(const float4*)&Xs[(dc * DCHUNK + dd) * ROWS_PER_BLK + r0];
                float4 e0 = *(const float4*)&Es[dd * KTILE + tk * 8];
                float4 e1 = *(const float4*)&Es[dd * KTILE + tk * 8 + 4];
                float ax[4] = {xv.x, xv.y, xv.z, xv.w};
                float ae[8] = {e0.x, e0.y, e0.z, e0.w, e1.x, e1.y, e1.z, e1.w};
                #pragma unroll
                for (int r = 0; r < 4; ++r)
                    #pragma unroll
                    for (int c = 0; c < 8; ++c)
                        acc[r][c] = __fmaf_rn(ax[r], ae[c], acc[r][c]);
            }
        }

        // Scores for this k-tile, exact reference rounding order:
        //   fl( fl(||x||^2 + ||e||^2) - fl(2*dot) )
        #pragma unroll
        for (int r = 0; r < 4; ++r) {
            float xsr = xs[r0 + r];
            #pragma unroll
            for (int c = 0; c < 8; ++c) {
                int k = kt * KTILE + tk * 8 + c;
                float t    = __fadd_rn(xsr, g_esq[k]);
                float dist = __fsub_rn(t, __fmul_rn(2.0f, acc[r][c]));
                if (dist < bestv[r]) { bestv[r] = dist; besti[r] = k; }
            }
        }
    }

    // Cross-thread argmin reduce per row (tie -> lowest index)
    #pragma unroll
    for (int r = 0; r < 4; ++r) {
        redv[(r0 + r) * 16 + tk] = bestv[r];
        redi[(r0 + r) * 16 + tk] = besti[r];
    }
    __syncthreads();
    if (tid < ROWS_PER_BLK) {
        float bv = redv[tid * 16];
        int   bi = redi[tid * 16];
        #pragma unroll
        for (int j = 1; j < 16; ++j) {
            float v = redv[tid * 16 + j];
            int   ii = redi[tid * 16 + j];
            if (v < bv || (v == bv && ii < bi)) { bv = v; bi = ii; }
        }
        bidx[tid] = bi;
        out[IDX_OFF + (size_t)b * TLEN + t0 + tid] = (float)bi;
    }
    __syncthreads();

    // Quantized output (straight-through: x + (q - x), reference rounding)
    // + loss partial sum in double
    double lsum = 0.0;
    #pragma unroll 4
    for (int i = tid; i < DIM * ROWS_PER_BLK; i += 256) {
        int d = i >> 6, r = i & 63;
        float q = g_emb_t[(size_t)d * K_CODES + bidx[r]];
        float x = Xs[i];
        float diff = __fsub_rn(q, x);
        lsum += (double)diff * (double)diff;
        out[(size_t)b * DIM * TLEN + (size_t)d * TLEN + t0 + r] = __fadd_rn(x, diff);
    }

    // Block-reduce loss, one atomic per block
    #pragma unroll
    for (int o = 16; o > 0; o >>= 1)
        lsum += __shfl_down_sync(0xffffffffu, lsum, o);
    __shared__ double lred[8];
    if ((tid & 31) == 0) lred[tid >> 5] = lsum;
    __syncthreads();
    if (tid == 0) {
        double s = 0.0;
        #pragma unroll
        for (int w = 0; w < 8; ++w) s += lred[w];
        atomicAdd(&g_loss, s);
    }
}

// ---------------------------------------------------------------------------
// finalize: loss = (q_latent + 0.25*e_latent) = 1.25 * mean(diff^2)
// ---------------------------------------------------------------------------
__global__ void vq_finalize(float* __restrict__ out) {
    out[LOSS_OFF] = (float)(g_loss * 1.25 / (double)QELEMS);
}

// ---------------------------------------------------------------------------
extern "C" void kernel_launch(void* const* d_in, const int* in_sizes, int n_in,
                              void* d_out, int out_size) {
    const float* x_in = (const float*)d_in[0];   // [B, D, T] float32
    const float* emb  = (const float*)d_in[1];   // [K, D]    float32
    float* out = (float*)d_out;

    static int smem_set = 0;
    const int smem_bytes = (DIM * ROWS_PER_BLK + DCHUNK * KTILE + ROWS_PER_BLK
                            + ROWS_PER_BLK * 16) * 4
                           + ROWS_PER_BLK * 16 * 4 + ROWS_PER_BLK * 4;
    if (!smem_set) {
        cudaFuncSetAttribute(vq_main, cudaFuncAttributeMaxDynamicSharedMemorySize,
                             smem_bytes);
        smem_set = 1;
    }

    vq_prep<<<K_CODES, DIM>>>(emb);
    vq_main<<<NROWS / ROWS_PER_BLK, 256, smem_bytes>>>(x_in, out);
    vq_finalize<<<1, 1>>>(out);
}

// round 2
// speedup vs baseline: 1.1752x; 1.1752x over previous
#include <cuda_runtime.h>
#include <cstdint>
#include <cfloat>

// Problem constants
#define K_CODES 1024
#define DIM     256
#define BATCH   32
#define TLEN    2048
#define NROWS   (BATCH * TLEN)          // 65536
#define QELEMS  ((size_t)BATCH * DIM * TLEN)  // 16777216
#define LOSS_OFF ((size_t)16777216)
#define IDX_OFF  ((size_t)16777217)

#define ROWS_PER_BLK 64
#define KTILE  128
#define DCHUNK 32

// Scratch (no allocations allowed)
__device__ float  g_emb_t[DIM * K_CODES];  // transposed codebook [d][k]
__device__ float  g_esq[K_CODES];          // ||e_k||^2
__device__ double g_loss;

// Packed dual-fp32 FMA: two independent IEEE fp32 RN FMAs per instruction.
// Bit-identical to two scalar __fmaf_rn calls.
__device__ __forceinline__ void ffma2(unsigned long long& acc,
                                      unsigned long long a,
                                      unsigned long long b) {
    asm("fma.rn.f32x2 %0, %1, %2, %0;" : "+l"(acc) : "l"(a), "l"(b));
}

__device__ __forceinline__ unsigned long long bcast2(float v) {
    unsigned long long r;
    asm("mov.b64 %0, {%1, %1};" : "=l"(r) : "r"(__float_as_uint(v)));
    return r;
}

__device__ __forceinline__ float lo32(unsigned long long v) {
    return __uint_as_float((unsigned)(v & 0xffffffffu));
}
__device__ __forceinline__ float hi32(unsigned long long v) {
    return __uint_as_float((unsigned)(v >> 32));
}

// ---------------------------------------------------------------------------
// prep: transpose codebook, per-code sum of squares, zero loss accumulator
// ---------------------------------------------------------------------------
__global__ void vq_prep(const float* __restrict__ emb) {
    int k = blockIdx.x;
    int d = threadIdx.x;
    float v = emb[k * DIM + d];
    g_emb_t[(size_t)d * K_CODES + k] = v;

    __shared__ float red[DIM];
    red[d] = v * v;
    __syncthreads();
    #pragma unroll
    for (int s = DIM / 2; s > 0; s >>= 1) {
        if (d < s) red[d] += red[d + s];
        __syncthreads();
    }
    if (d == 0) g_esq[k] = red[0];
    if (k == 0 && d == 0) g_loss = 0.0;
}

// ---------------------------------------------------------------------------
// main: distances + argmin + gather + straight-through write + loss partial
// grid: 1024 blocks x 256 threads
// ---------------------------------------------------------------------------
__global__ void __launch_bounds__(256)
vq_main(const float* __restrict__ x_in, float* __restrict__ out) {
    extern __shared__ float sm[];
    float* Xs   = sm;                                  // [256][64]
    float* Es   = Xs + DIM * ROWS_PER_BLK;             // [32][128]
    float* xs   = Es + DCHUNK * KTILE;                 // [64]
    float* redv = xs + ROWS_PER_BLK;                   // [64][16]
    int*   redi = (int*)(redv + ROWS_PER_BLK * 16);    // [64][16]
    int*   bidx = redi + ROWS_PER_BLK * 16;            // [64]

    const int blk = blockIdx.x;
    const int b   = blk >> 5;
    const int t0  = (blk & 31) * ROWS_PER_BLK;
    const int tid = threadIdx.x;

    const float* xbase = x_in + (size_t)b * DIM * TLEN + t0;

    // Load X tile: Xs[d][r] = input[b, d, t0+r]   (coalesced along r)
    #pragma unroll 4
    for (int i = tid; i < DIM * ROWS_PER_BLK; i += 256) {
        int d = i >> 6, r = i & 63;
        Xs[i] = xbase[(size_t)d * TLEN + r];
    }
    __syncthreads();

    // ||x||^2 per row (threads 0..63)
    if (tid < ROWS_PER_BLK) {
        float s = 0.f;
        #pragma unroll 8
        for (int d = 0; d < DIM; ++d) {
            float v = Xs[d * ROWS_PER_BLK + tid];
            s = __fmaf_rn(v, v, s);
        }
        xs[tid] = s;
    }
    __syncthreads();

    const int tr = tid & 15;   // row-group id (4 rows each)
    const int tk = tid >> 4;   // k-group id (8 codes each within a KTILE)
    const int r0 = tr * 4;

    float bestv[4];
    int   besti[4];
    #pragma unroll
    for (int r = 0; r < 4; ++r) { bestv[r] = FLT_MAX; besti[r] = 0; }

    for (int kt = 0; kt < K_CODES / KTILE; ++kt) {
        // acc2[r][c2]: packed pair = codes (tk*8 + 2*c2, tk*8 + 2*c2 + 1)
        unsigned long long acc2[4][4];
        #pragma unroll
        for (int r = 0; r < 4; ++r)
            #pragma unroll
            for (int c = 0; c < 4; ++c) acc2[r][c] = 0ull;

        for (int dc = 0; dc < DIM / DCHUNK; ++dc) {
            __syncthreads();   // protect Es from previous iteration's readers
            #pragma unroll 2
            for (int i = tid; i < DCHUNK * KTILE; i += 256) {
                int dd = i >> 7, kk = i & 127;
                Es[i] = g_emb_t[(size_t)(dc * DCHUNK + dd) * K_CODES + kt * KTILE + kk];
            }
            __syncthreads();

            #pragma unroll
            for (int dd = 0; dd < DCHUNK; ++dd) {
                float4 xv = *(const float4*)&Xs[(dc * DCHUNK + dd) * ROWS_PER_BLK + r0];
                // E pairs loaded directly as 64-bit lanes (16B aligned)
                ulonglong2 ep0 = *(const ulonglong2*)&Es[dd * KTILE + tk * 8];
                ulonglong2 ep1 = *(const ulonglong2*)&Es[dd * KTILE + tk * 8 + 4];
                unsigned long long e2[4] = {ep0.x, ep0.y, ep1.x, ep1.y};
                float ax[4] = {xv.x, xv.y, xv.z, xv.w};
                #pragma unroll
                for (int r = 0; r < 4; ++r) {
                    unsigned long long axx = bcast2(ax[r]);
                    #pragma unroll
                    for (int c = 0; c < 4; ++c)
                        ffma2(acc2[r][c], axx, e2[c]);
                }
            }
        }

        // Scores, exact reference rounding order:
        //   fl( fl(||x||^2 + ||e||^2) - fl(2*dot) )
        #pragma unroll
        for (int r = 0; r < 4; ++r) {
            float xsr = xs[r0 + r];
            #pragma unroll
            for (int c2 = 0; c2 < 4; ++c2) {
                float dlo = lo32(acc2[r][c2]);
                float dhi = hi32(acc2[r][c2]);
                int klo = kt * KTILE + tk * 8 + 2 * c2;
                float tlo = __fadd_rn(xsr, g_esq[klo]);
                float thi = __fadd_rn(xsr, g_esq[klo + 1]);
                float distlo = __fsub_rn(tlo, __fmul_rn(2.0f, dlo));
                float disthi = __fsub_rn(thi, __fmul_rn(2.0f, dhi));
                if (distlo < bestv[r]) { bestv[r] = distlo; besti[r] = klo; }
                if (disthi < bestv[r]) { bestv[r] = disthi; besti[r] = klo + 1; }
            }
        }
    }

    // Cross-thread argmin reduce per row (tie -> lowest index)
    #pragma unroll
    for (int r = 0; r < 4; ++r) {
        redv[(r0 + r) * 16 + tk] = bestv[r];
        redi[(r0 + r) * 16 + tk] = besti[r];
    }
    __syncthreads();
    if (tid < ROWS_PER_BLK) {
        float bv = redv[tid * 16];
        int   bi = redi[tid * 16];
        #pragma unroll
        for (int j = 1; j < 16; ++j) {
            float v  = redv[tid * 16 + j];
            int   ii = redi[tid * 16 + j];
            if (v < bv || (v == bv && ii < bi)) { bv = v; bi = ii; }
        }
        bidx[tid] = bi;
        out[IDX_OFF + (size_t)b * TLEN + t0 + tid] = (float)bi;
    }
    __syncthreads();

    // Quantized output (straight-through, reference rounding) + loss partial
    double lsum = 0.0;
    #pragma unroll 4
    for (int i = tid; i < DIM * ROWS_PER_BLK; i += 256) {
        int d = i >> 6, r = i & 63;
        float q = g_emb_t[(size_t)d * K_CODES + bidx[r]];
        float x = Xs[i];
        float diff = __fsub_rn(q, x);
        lsum += (double)diff * (double)diff;
        out[(size_t)b * DIM * TLEN + (size_t)d * TLEN + t0 + r] = __fadd_rn(x, diff);
    }

    #pragma unroll
    for (int o = 16; o > 0; o >>= 1)
        lsum += __shfl_down_sync(0xffffffffu, lsum, o);
    __shared__ double lred[8];
    if ((tid & 31) == 0) lred[tid >> 5] = lsum;
    __syncthreads();
    if (tid == 0) {
        double s = 0.0;
        #pragma unroll
        for (int w = 0; w < 8; ++w) s += lred[w];
        atomicAdd(&g_loss, s);
    }
}

// ---------------------------------------------------------------------------
__global__ void vq_finalize(float* __restrict__ out) {
    out[LOSS_OFF] = (float)(g_loss * 1.25 / (double)QELEMS);
}

// ---------------------------------------------------------------------------
extern "C" void kernel_launch(void* const* d_in, const int* in_sizes, int n_in,
                              void* d_out, int out_size) {
    const float* x_in = (const float*)d_in[0];   // [B, D, T] float32
    const float* emb  = (const float*)d_in[1];   // [K, D]    float32
    float* out = (float*)d_out;

    static int smem_set = 0;
    const int smem_bytes = (DIM * ROWS_PER_BLK + DCHUNK * KTILE + ROWS_PER_BLK
                            + ROWS_PER_BLK * 16) * 4
                           + ROWS_PER_BLK * 16 * 4 + ROWS_PER_BLK * 4;
    if (!smem_set) {
        cudaFuncSetAttribute(vq_main, cudaFuncAttributeMaxDynamicSharedMemorySize,
                             smem_bytes);
        smem_set = 1;
    }

    vq_prep<<<K_CODES, DIM>>>(emb);
    vq_main<<<NROWS / ROWS_PER_BLK, 256, smem_bytes>>>(x_in, out);
    vq_finalize<<<1, 1>>>(out);
}

// round 3
// speedup vs baseline: 2.4192x; 2.0584x over previous
#include <cuda_runtime.h>
#include <cuda_fp16.h>
#include <cstdint>
#include <cfloat>

// Problem constants
#define K_CODES 1024
#define DIM     256
#define BATCH   32
#define TLEN    2048
#define NROWS   (BATCH * TLEN)                 // 65536
#define QELEMS  ((size_t)BATCH * DIM * TLEN)   // 16777216
#define LOSS_OFF ((size_t)16777216)
#define IDX_OFF  ((size_t)16777217)

#define ROWS_PER_BLK 64
#define KTILE  128          // codes per streamed tile
#define NTILES (K_CODES / KTILE)   // 8
#define AST 264             // padded k-stride (fp16 elems): 264 ≡ 8 (mod 64) -> conflict-free frags

// Scratch (no allocations allowed)
__device__ float  g_emb_t[DIM * K_CODES];   // transposed codebook [d][k] (epilogue gather)
__device__ float  g_esq[K_CODES];           // ||e_k||^2 (exact fp32, shared by approx+rescore)
__device__ __half g_emb_h[K_CODES * DIM];   // fp16(1024 * e) [k][d]
__device__ double g_loss;

// Dynamic smem offsets (bytes)
#define OFF_AH    0
#define OFF_EH    33792                       // 64*264*2
#define OFF_TMIN  101376                      // + 128*264*2
#define OFF_MASK  103424                      // + 8*64*4
#define OFF_WIN   111616                      // + 8*64*4*4
#define OFF_XSQ   112128                      // + 64*8
#define OFF_MARG  112384
#define OFF_GMIN  112640
#define OFF_BIDX  112896
#define SMEM_SZ   113152

__device__ __forceinline__ void mma16816(float c[4], const unsigned a[4], const unsigned b[2]) {
    asm volatile(
        "mma.sync.aligned.m16n8k16.row.col.f32.f16.f16.f32 "
        "{%0,%1,%2,%3}, {%4,%5,%6,%7}, {%8,%9}, {%0,%1,%2,%3};"
        : "+f"(c[0]), "+f"(c[1]), "+f"(c[2]), "+f"(c[3])
        : "r"(a[0]), "r"(a[1]), "r"(a[2]), "r"(a[3]), "r"(b[0]), "r"(b[1]));
}

// ---------------------------------------------------------------------------
// prep: transpose codebook, ||e||^2, fp16 scaled codebook, zero loss
// grid: K_CODES blocks x DIM threads
// ---------------------------------------------------------------------------
__global__ void vq_prep(const float* __restrict__ emb) {
    int k = blockIdx.x;
    int d = threadIdx.x;
    float v = emb[k * DIM + d];
    g_emb_t[(size_t)d * K_CODES + k] = v;
    g_emb_h[(size_t)k * DIM + d] = __float2half(v * 1024.0f);

    __shared__ float red[DIM];
    red[d] = v * v;
    __syncthreads();
    #pragma unroll
    for (int s = DIM / 2; s > 0; s >>= 1) {
        if (d < s) red[d] += red[d + s];
        __syncthreads();
    }
    if (d == 0) g_esq[k] = red[0];
    if (k == 0 && d == 0) g_loss = 0.0;
}

// ---------------------------------------------------------------------------
// main: HMMA approx distances -> candidate masks -> exact rescore -> epilogue
// grid: 1024 blocks x 256 threads, ~110.5KB dyn smem (2 CTAs/SM)
// ---------------------------------------------------------------------------
__global__ void __launch_bounds__(256)
vq_main(const float* __restrict__ x_in, const float* __restrict__ emb,
        float* __restrict__ out) {
    extern __shared__ char sm[];
    __half* Ah   = (__half*)(sm + OFF_AH);     // [64][264] fp16(x)
    __half* Eh   = (__half*)(sm + OFF_EH);     // [128][264] fp16(1024e)
    int*    tmin = (int*)(sm + OFF_TMIN);      // [8][64] tile-min (float bits)
    unsigned* cmask = (unsigned*)(sm + OFF_MASK);  // [8][64][4]
    unsigned long long* winner = (unsigned long long*)(sm + OFF_WIN);  // [64]
    float*  xsqs = (float*)(sm + OFF_XSQ);     // [64]
    float*  marg = (float*)(sm + OFF_MARG);    // [64]
    float*  gmin = (float*)(sm + OFF_GMIN);    // [64]
    int*    bidx = (int*)(sm + OFF_BIDX);      // [64]

    const int blk = blockIdx.x;
    const int b   = blk >> 5;
    const int t0  = (blk & 31) * ROWS_PER_BLK;
    const int tid = threadIdx.x;
    const float* xbase = x_in + (size_t)b * DIM * TLEN + t0;

    // init scratch
    for (int i = tid; i < NTILES * ROWS_PER_BLK; i += 256) tmin[i] = 0x7f800000;
    for (int i = tid; i < NTILES * ROWS_PER_BLK * 4; i += 256) cmask[i] = 0u;
    if (tid < ROWS_PER_BLK) winner[tid] = ~0ull;

    // A tile: fp16(x), Ah[r][d]  (global loads coalesced along r)
    #pragma unroll 4
    for (int i = tid; i < DIM * ROWS_PER_BLK; i += 256) {
        int d = i >> 6, r = i & 63;
        Ah[r * AST + d] = __float2half(xbase[(size_t)d * TLEN + r]);
    }

    // ||x||^2 (exact fp32 chain, d ascending) + per-row error margin
    if (tid < ROWS_PER_BLK) {
        float s = 0.f, sa = 0.f;
        #pragma unroll 8
        for (int d = 0; d < DIM; ++d) {
            float v = xbase[(size_t)d * TLEN + tid];
            s = __fmaf_rn(v, v, s);
            sa += fabsf(v);
        }
        xsqs[tid] = s;
        // 4 * (Sx/1024)*2^-10 + slack: covers fp16 rounding of x,e + fp32
        // accumulation reorder + final-subtraction quanta at magnitude ~256
        marg[tid] = sa * (4.0f / (1024.0f * 1024.0f)) + 3e-4f;
    }
    __syncthreads();

    const int lane = tid & 31, w = tid >> 5;
    const int g = lane >> 2, tk2 = lane & 3;
    const int mw = w & 1, nw = w >> 1;
    const int r0 = mw * 32;   // warp's 32 rows
    const int c0 = nw * 32;   // warp's 32 codes within 128-code tile

    for (int kt = 0; kt < NTILES; ++kt) {
        __syncthreads();   // protect Eh from previous tile's readers
        // Load E tile: one code row (512B) per warp-iteration, coalesced
        for (int i = tid; i < KTILE * 32; i += 256) {
            int code = i >> 5, j = i & 31;
            const uint4* src = (const uint4*)(g_emb_h + (size_t)(kt * KTILE + code) * DIM) + j;
            uint4* dst = (uint4*)((char*)Eh + code * (AST * 2)) + j;
            *dst = *src;
        }
        __syncthreads();

        float acc[2][4][4];
        #pragma unroll
        for (int mm = 0; mm < 2; ++mm)
            #pragma unroll
            for (int nn = 0; nn < 4; ++nn)
                #pragma unroll
                for (int c = 0; c < 4; ++c) acc[mm][nn][c] = 0.f;

        #pragma unroll 4
        for (int kb = 0; kb < DIM; kb += 16) {
            unsigned a[2][4], bf[4][2];
            #pragma unroll
            for (int mm = 0; mm < 2; ++mm) {
                const __half* ap = &Ah[(r0 + mm * 16 + g) * AST + kb + 2 * tk2];
                a[mm][0] = *(const unsigned*)ap;
                a[mm][1] = *(const unsigned*)(ap + 8 * AST);
                a[mm][2] = *(const unsigned*)(ap + 8);
                a[mm][3] = *(const unsigned*)(ap + 8 * AST + 8);
            }
            #pragma unroll
            for (int nn = 0; nn < 4; ++nn) {
                const __half* bp = &Eh[(c0 + nn * 8 + g) * AST + kb + 2 * tk2];
                bf[nn][0] = *(const unsigned*)bp;
                bf[nn][1] = *(const unsigned*)(bp + 8);
            }
            #pragma unroll
            for (int mm = 0; mm < 2; ++mm)
                #pragma unroll
                for (int nn = 0; nn < 4; ++nn)
                    mma16816(acc[mm][nn], a[mm], bf[nn]);
        }

        // acc -> approx dist; per-lane per-row min
        float rmin[2][2] = {{FLT_MAX, FLT_MAX}, {FLT_MAX, FLT_MAX}};
        #pragma unroll
        for (int mm = 0; mm < 2; ++mm)
            #pragma unroll
            for (int nn = 0; nn < 4; ++nn)
                #pragma unroll
                for (int c = 0; c < 4; ++c) {
                    int kloc = c0 + nn * 8 + 2 * tk2 + (c & 1);
                    int row  = r0 + mm * 16 + g + (c >> 1) * 8;
                    int k    = kt * KTILE + kloc;
                    // dot = acc/1024 (E scaled by 1024); 2*dot = acc/512 exact scale
                    float d = __fsub_rn(__fadd_rn(xsqs[row], g_esq[k]),
                                        __fmul_rn(acc[mm][nn][c], 0.001953125f));
                    acc[mm][nn][c] = d;
                    if (d < rmin[mm][c >> 1]) rmin[mm][c >> 1] = d;
                }
        // reduce over tk2 quad -> tile-min per row
        #pragma unroll
        for (int mm = 0; mm < 2; ++mm)
            #pragma unroll
            for (int ch = 0; ch < 2; ++ch) {
                float v = rmin[mm][ch];
                v = fminf(v, __shfl_xor_sync(0xffffffffu, v, 1));
                v = fminf(v, __shfl_xor_sync(0xffffffffu, v, 2));
                if (tk2 == 0)
                    atomicMin(&tmin[kt * 64 + r0 + mm * 16 + g + ch * 8],
                              __float_as_int(v));
            }
        __syncthreads();
        // candidate mask: approx dist within margin of tile-min
        #pragma unroll
        for (int mm = 0; mm < 2; ++mm)
            #pragma unroll
            for (int nn = 0; nn < 4; ++nn)
                #pragma unroll
                for (int c = 0; c < 4; ++c) {
                    int kloc = c0 + nn * 8 + 2 * tk2 + (c & 1);
                    int row  = r0 + mm * 16 + g + (c >> 1) * 8;
                    float lim = __int_as_float(tmin[kt * 64 + row]) + marg[row];
                    if (acc[mm][nn][c] <= lim)
                        atomicOr(&cmask[(kt * 64 + row) * 4 + (kloc >> 5)],
                                 1u << (kloc & 31));
                }
    }
    __syncthreads();

    // global approx min per row
    if (tid < ROWS_PER_BLK) {
        float m = FLT_MAX;
        #pragma unroll
        for (int t = 0; t < NTILES; ++t)
            m = fminf(m, __int_as_float(tmin[t * 64 + tid]));
        gmin[tid] = m;
    }
    __syncthreads();

    // exact rescore of candidates (identical fp32 fma chain as rounds 1-2)
    for (int p = tid; p < ROWS_PER_BLK * NTILES; p += 256) {
        int row = p >> 3, t = p & 7;
        if (__int_as_float(tmin[t * 64 + row]) <= gmin[row] + marg[row]) {
            #pragma unroll
            for (int w4 = 0; w4 < 4; ++w4) {
                unsigned m = cmask[(t * 64 + row) * 4 + w4];
                while (m) {
                    int bit = __ffs(m) - 1; m &= m - 1;
                    int k = t * KTILE + w4 * 32 + bit;
                    const float* ek = emb + (size_t)k * DIM;
                    float accv = 0.f;
                    #pragma unroll 8
                    for (int d = 0; d < DIM; ++d)
                        accv = __fmaf_rn(xbase[(size_t)d * TLEN + row], ek[d], accv);
                    float dd = __fsub_rn(__fadd_rn(xsqs[row], g_esq[k]),
                                         __fmul_rn(2.0f, accv));
                    unsigned long long key =
                        ((unsigned long long)__float_as_uint(dd) << 32) | (unsigned)k;
                    atomicMin(&winner[row], key);
                }
            }
        }
    }
    __syncthreads();

    if (tid < ROWS_PER_BLK) {
        int bi = (int)(winner[tid] & 0xffffffffu);
        bidx[tid] = bi;
        out[IDX_OFF + (size_t)b * TLEN + t0 + tid] = (float)bi;
    }
    __syncthreads();

    // quantized output (straight-through, reference rounding) + loss partial
    double lsum = 0.0;
    #pragma unroll 4
    for (int i = tid; i < DIM * ROWS_PER_BLK; i += 256) {
        int d = i >> 6, r = i & 63;
        float q = g_emb_t[(size_t)d * K_CODES + bidx[r]];
        float x = xbase[(size_t)d * TLEN + r];
        float diff = __fsub_rn(q, x);
        lsum += (double)diff * (double)diff;
        out[(size_t)b * DIM * TLEN + (size_t)d * TLEN + t0 + r] = __fadd_rn(x, diff);
    }
    #pragma unroll
    for (int o = 16; o > 0; o >>= 1)
        lsum += __shfl_down_sync(0xffffffffu, lsum, o);
    __shared__ double lred[8];
    if ((tid & 31) == 0) lred[tid >> 5] = lsum;
    __syncthreads();
    if (tid == 0) {
        double s = 0.0;
        #pragma unroll
        for (int wv = 0; wv < 8; ++wv) s += lred[wv];
        atomicAdd(&g_loss, s);
    }
}

// ---------------------------------------------------------------------------
__global__ void vq_finalize(float* __restrict__ out) {
    out[LOSS_OFF] = (float)(g_loss * 1.25 / (double)QELEMS);
}

// ---------------------------------------------------------------------------
extern "C" void kernel_launch(void* const* d_in, const int* in_sizes, int n_in,
                              void* d_out, int out_size) {
    const float* x_in = (const float*)d_in[0];   // [B, D, T] float32
    const float* emb  = (const float*)d_in[1];   // [K, D]    float32
    float* out = (float*)d_out;

    static int smem_set = 0;
    if (!smem_set) {
        cudaFuncSetAttribute(vq_main, cudaFuncAttributeMaxDynamicSharedMemorySize,
                             SMEM_SZ);
        smem_set = 1;
    }

    vq_prep<<<K_CODES, DIM>>>(emb);
    vq_main<<<NROWS / ROWS_PER_BLK, 256, SMEM_SZ>>>(x_in, emb, out);
    vq_finalize<<<1, 1>>>(out);
}

// round 5
// speedup vs baseline: 2.5579x; 1.0574x over previous
#include <cuda_runtime.h>
#include <cuda_fp16.h>
#include <cstdint>
#include <cfloat>

// Problem constants
#define K_CODES 1024
#define DIM     256
#define BATCH   32
#define TLEN    2048
#define NROWS   (BATCH * TLEN)                 // 65536
#define QELEMS  ((size_t)BATCH * DIM * TLEN)   // 16777216
#define LOSS_OFF ((size_t)16777216)
#define IDX_OFF  ((size_t)16777217)

#define ROWS 128
#define THREADS 512
#define KTILE  128
#define NTILES (K_CODES / KTILE)   // 8
#define AST 280                    // padded k-stride (halves): conflict-free

// Scratch (no allocations allowed)
__device__ float  g_emb_t[DIM * K_CODES];   // transposed codebook [d][k]
__device__ float  g_esq[K_CODES];           // ||e_k||^2 exact (rescore)
__device__ float  g_sesq[K_CODES];          // 512 * ||e_k||^2 (approx ranking)
__device__ __half g_emb_h[K_CODES * DIM];   // fp16(1024 * e) [k][d]
__device__ double g_loss;

// Dynamic smem offsets (bytes)
#define OFF_AH    0                      // [128][280] half
#define OFF_EH    71680                  // [128][280] half
#define OFF_SESQ  143360                 // [128] float
#define OFF_TMIN  143872                 // [8][128] unsigned (encoded float)
#define OFF_MASK  147968                 // [8][128][4] unsigned
#define OFF_WIN   164352                 // [128] u64
#define OFF_XSQ   165376                 // [128] float
#define OFF_MARG  165888                 // [128] float (margin in dist'-units)
#define OFF_GMIN  166400                 // [128] float
#define OFF_BIDX  166912                 // [128] int
#define SMEM_SZ   167424

__device__ __forceinline__ void mma16816(float c[4], const unsigned a[4], const unsigned b[2]) {
    asm volatile(
        "mma.sync.aligned.m16n8k16.row.col.f32.f16.f16.f32 "
        "{%0,%1,%2,%3}, {%4,%5,%6,%7}, {%8,%9}, {%0,%1,%2,%3};"
        : "+f"(c[0]), "+f"(c[1]), "+f"(c[2]), "+f"(c[3])
        : "r"(a[0]), "r"(a[1]), "r"(a[2]), "r"(a[3]), "r"(b[0]), "r"(b[1]));
}

__device__ __forceinline__ void ldsm_x4(unsigned r[4], const void* p) {
    unsigned addr = (unsigned)__cvta_generic_to_shared(p);
    asm volatile("ldmatrix.sync.aligned.m8n8.x4.shared.b16 {%0,%1,%2,%3}, [%4];"
                 : "=r"(r[0]), "=r"(r[1]), "=r"(r[2]), "=r"(r[3]) : "r"(addr));
}

// monotone float<->unsigned map (works for negatives)
__device__ __forceinline__ unsigned fenc(float f) {
    unsigned b = __float_as_uint(f);
    return b ^ ((unsigned)((int)b >> 31) | 0x80000000u);
}
__device__ __forceinline__ float fdec(unsigned u) {
    unsigned b = u ^ (((int)u >= 0) ? 0xFFFFFFFFu : 0x80000000u);
    return __uint_as_float(b);
}

// ---------------------------------------------------------------------------
// prep: transpose codebook, ||e||^2 (+512x), fp16 scaled codebook, zero loss
// ---------------------------------------------------------------------------
__global__ void vq_prep(const float* __restrict__ emb) {
    int k = blockIdx.x;
    int d = threadIdx.x;
    float v = emb[k * DIM + d];
    g_emb_t[(size_t)d * K_CODES + k] = v;
    g_emb_h[(size_t)k * DIM + d] = __float2half(v * 1024.0f);

    __shared__ float red[DIM];
    red[d] = v * v;
    __syncthreads();
    #pragma unroll
    for (int s = DIM / 2; s > 0; s >>= 1) {
        if (d < s) red[d] += red[d + s];
        __syncthreads();
    }
    if (d == 0) { g_esq[k] = red[0]; g_sesq[k] = 512.0f * red[0]; }
    if (k == 0 && d == 0) g_loss = 0.0;
}

// ---------------------------------------------------------------------------
// main: HMMA approx (esq folded) -> candidate masks -> exact rescore -> epilogue
// grid: 512 blocks x 512 threads, ~163.5KB dyn smem (1 CTA/SM)
// ---------------------------------------------------------------------------
__global__ void __launch_bounds__(THREADS)
vq_main(const float* __restrict__ x_in, const float* __restrict__ emb,
        float* __restrict__ out) {
    extern __shared__ char sm[];
    __half* Ah   = (__half*)(sm + OFF_AH);
    __half* Eh   = (__half*)(sm + OFF_EH);
    float*  sesq = (float*)(sm + OFF_SESQ);
    unsigned* tmin = (unsigned*)(sm + OFF_TMIN);
    unsigned* cmask = (unsigned*)(sm + OFF_MASK);
    unsigned long long* winner = (unsigned long long*)(sm + OFF_WIN);
    float*  xsqs = (float*)(sm + OFF_XSQ);
    float*  margA = (float*)(sm + OFF_MARG);
    float*  gmin = (float*)(sm + OFF_GMIN);
    int*    bidx = (int*)(sm + OFF_BIDX);

    const int blk = blockIdx.x;
    const int b   = blk >> 4;
    const int t0  = (blk & 15) * ROWS;
    const int tid = threadIdx.x;
    const float* xbase = x_in + (size_t)b * DIM * TLEN + t0;

    // init scratch
    for (int i = tid; i < NTILES * ROWS; i += THREADS) tmin[i] = 0xFFFFFFFFu;
    for (int i = tid; i < NTILES * ROWS * 4; i += THREADS) cmask[i] = 0u;
    if (tid < ROWS) winner[tid] = ~0ull;

    // A tile: fp16(x) as half2 pairs (coalesced along r)
    for (int i = tid; i < 128 * ROWS; i += THREADS) {
        int d2 = i >> 7, r = i & 127;
        float v0 = xbase[(size_t)(2 * d2) * TLEN + r];
        float v1 = xbase[(size_t)(2 * d2 + 1) * TLEN + r];
        *(__half2*)&Ah[r * AST + 2 * d2] = __floats2half2_rn(v0, v1);
    }

    // ||x||^2 (exact sequential fp32 chain) + margin (dist'-units = 512x)
    if (tid < ROWS) {
        float s = 0.f, sa = 0.f;
        #pragma unroll 8
        for (int d = 0; d < DIM; ++d) {
            float v = xbase[(size_t)d * TLEN + tid];
            s = __fmaf_rn(v, v, s);
            sa += fabsf(v);
        }
        xsqs[tid] = s;
        margA[tid] = 512.0f * (sa * (4.0f / (1024.0f * 1024.0f)) + 3e-4f);
    }
    __syncthreads();

    const int lane = tid & 31, w = tid >> 5;
    const int g = lane >> 2, tk2 = lane & 3;
    const int mw = w & 3, nw = w >> 2;
    const int r0 = mw * 32;   // warp's 32 rows
    const int c0 = nw * 32;   // warp's 32 codes within 128-code tile

    for (int kt = 0; kt < NTILES; ++kt) {
        __syncthreads();   // protect Eh/sesq from previous tile's readers
        // Stage E tile: 128 codes x 256 halves = 512B/code (32 uint4), coalesced
        for (int i = tid; i < KTILE * 32; i += THREADS) {
            int code = i >> 5, j = i & 31;
            uint4 v = ((const uint4*)(g_emb_h + (size_t)(kt * KTILE + code) * DIM))[j];
            *(uint4*)(sm + OFF_EH + code * (AST * 2) + j * 16) = v;
        }
        if (tid < KTILE) sesq[tid] = g_sesq[kt * KTILE + tid];
        __syncthreads();

        float acc[2][4][4];
        #pragma unroll
        for (int mm = 0; mm < 2; ++mm)
            #pragma unroll
            for (int nn = 0; nn < 4; ++nn)
                #pragma unroll
                for (int c = 0; c < 4; ++c) acc[mm][nn][c] = 0.f;

        #pragma unroll
        for (int kb = 0; kb < DIM; kb += 16) {
            unsigned a[2][4], bf[4][2];
            #pragma unroll
            for (int mm = 0; mm < 2; ++mm) {
                int rowA = r0 + mm * 16 + (lane & 15);
                int colA = kb + ((lane & 16) >> 1);
                ldsm_x4(a[mm], &Ah[rowA * AST + colA]);
            }
            #pragma unroll
            for (int nn2 = 0; nn2 < 2; ++nn2) {
                int nrow = c0 + nn2 * 16 + (lane & 7) + ((lane & 16) >> 1);
                int colB = kb + (lane & 8);
                unsigned r4[4];
                ldsm_x4(r4, &Eh[nrow * AST + colB]);
                bf[2 * nn2][0] = r4[0]; bf[2 * nn2][1] = r4[1];
                bf[2 * nn2 + 1][0] = r4[2]; bf[2 * nn2 + 1][1] = r4[3];
            }
            #pragma unroll
            for (int mm = 0; mm < 2; ++mm)
                #pragma unroll
                for (int nn = 0; nn < 4; ++nn)
                    mma16816(acc[mm][nn], a[mm], bf[nn]);
        }

        // per-thread esq terms for its 8 distinct kloc values
        float sq[8];
        #pragma unroll
        for (int nn = 0; nn < 4; ++nn) {
            sq[nn * 2]     = sesq[c0 + nn * 8 + 2 * tk2];
            sq[nn * 2 + 1] = sesq[c0 + nn * 8 + 2 * tk2 + 1];
        }

        // pass 1: dist' = 512*esq - acc; per-row min (register-only)
        float rmin[2][2] = {{FLT_MAX, FLT_MAX}, {FLT_MAX, FLT_MAX}};
        #pragma unroll
        for (int mm = 0; mm < 2; ++mm)
            #pragma unroll
            for (int nn = 0; nn < 4; ++nn)
                #pragma unroll
                for (int c = 0; c < 4; ++c) {
                    float d = __fsub_rn(sq[nn * 2 + (c & 1)], acc[mm][nn][c]);
                    acc[mm][nn][c] = d;
                    rmin[mm][c >> 1] = fminf(rmin[mm][c >> 1], d);
                }
        #pragma unroll
        for (int mm = 0; mm < 2; ++mm)
            #pragma unroll
            for (int ch = 0; ch < 2; ++ch) {
                float v = rmin[mm][ch];
                v = fminf(v, __shfl_xor_sync(0xffffffffu, v, 1));
                v = fminf(v, __shfl_xor_sync(0xffffffffu, v, 2));
                if (tk2 == 0)
                    atomicMin(&tmin[kt * ROWS + r0 + mm * 16 + g + ch * 8], fenc(v));
            }
        __syncthreads();

        // pass 2: flag candidates within margin of tile-min
        float lim[2][2];
        #pragma unroll
        for (int mm = 0; mm < 2; ++mm)
            #pragma unroll
            for (int ch = 0; ch < 2; ++ch) {
                int row = r0 + mm * 16 + g + ch * 8;
                lim[mm][ch] = fdec(tmin[kt * ROWS + row]) + margA[row];
            }
        #pragma unroll
        for (int mm = 0; mm < 2; ++mm)
            #pragma unroll
            for (int nn = 0; nn < 4; ++nn)
                #pragma unroll
                for (int c = 0; c < 4; ++c) {
                    if (acc[mm][nn][c] <= lim[mm][c >> 1]) {
                        int kloc = c0 + nn * 8 + 2 * tk2 + (c & 1);
                        int row  = r0 + mm * 16 + g + (c >> 1) * 8;
                        atomicOr(&cmask[(kt * ROWS + row) * 4 + (kloc >> 5)],
                                 1u << (kloc & 31));
                    }
                }
    }
    __syncthreads();

    // global approx min per row (dist'-units)
    if (tid < ROWS) {
        float m = FLT_MAX;
        #pragma unroll
        for (int t = 0; t < NTILES; ++t)
            m = fminf(m, fdec(tmin[t * ROWS + tid]));
        gmin[tid] = m;
    }
    __syncthreads();

    // exact rescore of candidates (identical fp32 fma chain as rounds 1-3)
    for (int p = tid; p < ROWS * NTILES; p += THREADS) {
        int row = p >> 3, t = p & 7;
        if (fdec(tmin[t * ROWS + row]) <= gmin[row] + margA[row]) {
            #pragma unroll
            for (int w4 = 0; w4 < 4; ++w4) {
                unsigned m = cmask[(t * ROWS + row) * 4 + w4];
                while (m) {
                    int bit = __ffs(m) - 1; m &= m - 1;
                    int k = t * KTILE + w4 * 32 + bit;
                    const float* ek = emb + (size_t)k * DIM;
                    float accv = 0.f;
                    #pragma unroll 8
                    for (int d = 0; d < DIM; ++d)
                        accv = __fmaf_rn(xbase[(size_t)d * TLEN + row], ek[d], accv);
                    float dd = __fsub_rn(__fadd_rn(xsqs[row], g_esq[k]),
                                         __fmul_rn(2.0f, accv));
                    unsigned long long key =
                        ((unsigned long long)__float_as_uint(dd) << 32) | (unsigned)k;
                    atomicMin(&winner[row], key);
                }
            }
        }
    }
    __syncthreads();

    if (tid < ROWS) {
        int bi = (int)(winner[tid] & 0xffffffffu);
        bidx[tid] = bi;
        out[IDX_OFF + (size_t)b * TLEN + t0 + tid] = (float)bi;
    }
    __syncthreads();

    // quantized output (straight-through, reference rounding) + loss partial
    double lsum = 0.0;
    #pragma unroll 4
    for (int i = tid; i < DIM * ROWS; i += THREADS) {
        int d = i >> 7, r = i & 127;
        float q = g_emb_t[(size_t)d * K_CODES + bidx[r]];
        float x = xbase[(size_t)d * TLEN + r];
        float diff = __fsub_rn(q, x);
        lsum += (double)diff * (double)diff;
        out[(size_t)b * DIM * TLEN + (size_t)d * TLEN + t0 + r] = __fadd_rn(x, diff);
    }
    #pragma unroll
    for (int o = 16; o > 0; o >>= 1)
        lsum += __shfl_down_sync(0xffffffffu, lsum, o);
    __shared__ double lred[16];
    if ((tid & 31) == 0) lred[tid >> 5] = lsum;
    __syncthreads();
    if (tid == 0) {
        double s = 0.0;
        #pragma unroll
        for (int wv = 0; wv < 16; ++wv) s += lred[wv];
        atomicAdd(&g_loss, s);
    }
}

// ---------------------------------------------------------------------------
__global__ void vq_finalize(float* __restrict__ out) {
    out[LOSS_OFF] = (float)(g_loss * 1.25 / (double)QELEMS);
}

// ---------------------------------------------------------------------------
extern "C" void kernel_launch(void* const* d_in, const int* in_sizes, int n_in,
                              void* d_out, int out_size) {
    const float* x_in = (const float*)d_in[0];   // [B, D, T] float32
    const float* emb  = (const float*)d_in[1];   // [K, D]    float32
    float* out = (float*)d_out;

    static int smem_set = 0;
    if (!smem_set) {
        cudaFuncSetAttribute(vq_main, cudaFuncAttributeMaxDynamicSharedMemorySize,
                             SMEM_SZ);
        smem_set = 1;
    }

    vq_prep<<<K_CODES, DIM>>>(emb);
    vq_main<<<NROWS / ROWS, THREADS, SMEM_SZ>>>(x_in, emb, out);
    vq_finalize<<<1, 1>>>(out);
}